// round 5
// baseline (speedup 1.0000x reference)
#include <cuda_runtime.h>
#include <math.h>

// Problem constants
#define NB       128
#define TLEN     160000
#define NFFT     400
#define HOP      160
#define NFRAMES  1001          // 1 + TLEN/HOP
#define NFREQ    201           // NFFT/2 + 1
#define NMELS    80
#define FPB      32            // frames per block
#define NTILES   ((NFRAMES + FPB - 1) / FPB)   // 32
#define NH       199           // symmetric half: n = 1..199
#define NROWS    200           // NH padded to even (row 199 zeroed)
#define NTHREADS 256
#define SPAN     (HOP * (FPB - 1) + NFFT)      // 5360 samples per block

// Swizzled raw-sample layout: +1 float per 32 so stride-160 accesses spread banks.
#define SWZ(i)   ((i) + ((i) >> 5))
#define SU_SIZE  (FPB * NFREQ)                 // 6432 >= SWZ(SPAN-1)+1 = 5527

// Twiddle table: row r corresponds to n = r+1; (c, s) pairs; rows >= NH are zero.
// KPAD columns so k = kt + 64j addressing stays in-bounds; prefetch reads row r+2.
#define KPAD     256
#define ROWS_PAD (NROWS + 2)
__device__ float2 g_cs[ROWS_PAD * KPAD];
__device__ int2   g_mrange[NMELS];

// One combined setup kernel (twiddles + mel ranges)
__global__ void setup_kernel(const float* __restrict__ fb) {
    if (blockIdx.x == gridDim.x - 1) {
        int m = threadIdx.x;
        if (m < NMELS) {
            int ks = NFREQ, ke = 0;
            for (int k = 0; k < NFREQ; k++) {
                if (fb[m * NFREQ + k] != 0.0f) { if (k < ks) ks = k; ke = k + 1; }
            }
            if (ke < ks) { ks = 0; ke = 0; }
            g_mrange[m] = make_int2(ks, ke);
        }
        return;
    }
    int idx = blockIdx.x * blockDim.x + threadIdx.x;
    if (idx >= ROWS_PAD * KPAD) return;
    int r = idx / KPAD;                 // r = n-1
    int k = idx - r * KPAD;
    float2 v = make_float2(0.0f, 0.0f);
    if (r < NH) {
        long long p = ((long long)(r + 1) * (long long)k) % NFFT;
        double a = (double)p * (6.283185307179586476925286766559 / (double)NFFT);
        v = make_float2((float)cos(a), (float)sin(a));
    }
    g_cs[idx] = v;
}

// ---- packed fp32x2 helpers (sm_100a) ----
__device__ __forceinline__ unsigned long long pack2(float lo, float hi) {
    unsigned long long r;
    asm("mov.b64 %0, {%1, %2};" : "=l"(r) : "f"(lo), "f"(hi));
    return r;
}
__device__ __forceinline__ void unpack2(unsigned long long v, float& lo, float& hi) {
    asm("mov.b64 {%0, %1}, %2;" : "=f"(lo), "=f"(hi) : "l"(v));
}
__device__ __forceinline__ void ffma2(unsigned long long& acc,
                                      unsigned long long a,
                                      unsigned long long b) {
    asm("fma.rn.f32x2 %0, %1, %2, %0;" : "+l"(acc) : "l"(a), "l"(b));
}

__global__ __launch_bounds__(NTHREADS, 2)
void melspec_kernel(const float* __restrict__ audio,
                    const float* __restrict__ window,
                    const float* __restrict__ fb,
                    float* __restrict__ out) {
    // dynamic smem:
    //  [0, SU_SIZE)          raw samples (swizzled) -> later power spectrum [f][k]
    //  [SU_SIZE, +NROWS*FPB*2) eo combos: row r holds 32 float2 (e,o); row 199 zero
    //  [.., +FPB]            x0w   [.., +FPB] x200w
    extern __shared__ float smem[];
    float* s_u    = smem;
    float* s_eo   = smem + SU_SIZE;                 // float2-ish, 2 floats per entry
    float* s_x0   = s_eo + NROWS * FPB * 2;
    float* s_x200 = s_x0 + FPB;

    const int tid    = threadIdx.x;
    const int b      = blockIdx.y;
    const int tile   = blockIdx.x;
    const int frame0 = tile * FPB;
    const float* x   = audio + (size_t)b * TLEN;
    const int base   = frame0 * HOP - (NFFT / 2);

    // ---- Phase 1: load raw samples with reflect padding (swizzled store) ----
    for (int i = tid; i < SPAN; i += NTHREADS) {
        int j = base + i;
        if (j < 0) j = -j;
        else if (j >= TLEN) j = 2 * TLEN - 2 - j;
        s_u[SWZ(i)] = x[j];
    }
    __syncthreads();

    // ---- Phase 2: interleaved (e,o) windowed combinations ----
    if (tid < FPB) {
        s_x0[tid]   = window[0]        * s_u[SWZ(tid * HOP)];
        s_x200[tid] = window[NFFT / 2] * s_u[SWZ(tid * HOP + NFFT / 2)];
    }
    for (int idx = tid; idx < NROWS * FPB; idx += NTHREADS) {
        int r = idx >> 5;                // FPB == 32
        int f = idx & (FPB - 1);
        float e = 0.0f, o = 0.0f;
        if (r < NH) {
            int n = r + 1;
            float w = window[n];
            float a = s_u[SWZ(f * HOP + n)];
            float c = s_u[SWZ(f * HOP + NFFT - n)];
            e = w * (a + c);
            o = w * (a - c);
        }
        ((float2*)s_eo)[idx] = make_float2(e, o);
    }
    __syncthreads();

    // ---- Phase 3: half-length real DFT, joint (re,im) f32x2 accumulation ----
    // thread -> kt = tid&63 handles k in {kt, kt+64, kt+128, kt+192};
    //           g = tid>>6 handles frames [8g, 8g+8)
    const int kt  = tid & 63;
    const int g   = tid >> 6;
    const int fb0 = g * 8;

    unsigned long long acc[4][8];
    {
        float sgn = (kt & 1) ? -1.0f : 1.0f;   // parity of k = parity of kt
        #pragma unroll
        for (int h = 0; h < 8; h++) {
            float r0 = s_x0[fb0 + h] + sgn * s_x200[fb0 + h];
            unsigned long long v = pack2(r0, 0.0f);
            #pragma unroll
            for (int j = 0; j < 4; j++) acc[j][h] = v;
        }
    }

    const unsigned long long* csTab =
        (const unsigned long long*)g_cs + kt;       // column base
    unsigned long long cs0[4], cs1[4];
    #pragma unroll
    for (int j = 0; j < 4; j++) cs0[j] = csTab[0 * KPAD + 64 * j];
    #pragma unroll
    for (int j = 0; j < 4; j++) cs1[j] = csTab[1 * KPAD + 64 * j];

    #pragma unroll 2
    for (int n = 0; n < NROWS; n++) {
        unsigned long long csN[4];
        #pragma unroll
        for (int j = 0; j < 4; j++)
            csN[j] = csTab[(n + 2) * KPAD + 64 * j];   // rows >= NH are zeros

        const ulonglong2* eo = (const ulonglong2*)(s_eo + n * (FPB * 2) + fb0 * 2);
        ulonglong2 p0 = eo[0], p1 = eo[1], p2 = eo[2], p3 = eo[3];

        #pragma unroll
        for (int j = 0; j < 4; j++) {
            unsigned long long cs = cs0[j];
            ffma2(acc[j][0], cs, p0.x);
            ffma2(acc[j][1], cs, p0.y);
            ffma2(acc[j][2], cs, p1.x);
            ffma2(acc[j][3], cs, p1.y);
            ffma2(acc[j][4], cs, p2.x);
            ffma2(acc[j][5], cs, p2.y);
            ffma2(acc[j][6], cs, p3.x);
            ffma2(acc[j][7], cs, p3.y);
        }
        #pragma unroll
        for (int j = 0; j < 4; j++) { cs0[j] = cs1[j]; cs1[j] = csN[j]; }
    }
    __syncthreads();     // raw samples dead; reuse s_u as power spectrum [f][k]

    #pragma unroll
    for (int j = 0; j < 4; j++) {
        int k = kt + 64 * j;
        if (k < NFREQ) {
            #pragma unroll
            for (int h = 0; h < 8; h++) {
                float re, im;
                unpack2(acc[j][h], re, im);
                s_u[(fb0 + h) * NFREQ + k] = re * re + im * im;
            }
        }
    }
    __syncthreads();

    // ---- Phase 4: sparse mel projection + log ----
    const int f  = tid & (FPB - 1);
    const int mb = tid >> 5;                     // 0..7
    int nvalid = NFRAMES - frame0;
    if (nvalid > FPB) nvalid = FPB;
    const float* pr = s_u + f * NFREQ;
    for (int m = mb; m < NMELS; m += NTHREADS / FPB) {
        int2 r = g_mrange[m];
        float acc4 = 0.0f;
        const float* fbr = fb + m * NFREQ;
        for (int kk = r.x; kk < r.y; kk++)
            acc4 = fmaf(fbr[kk], pr[kk], acc4);
        if (f < nvalid)
            out[((size_t)b * NMELS + m) * NFRAMES + frame0 + f] =
                logf(acc4 + 1.1920929e-07f);
    }
}

extern "C" void kernel_launch(void* const* d_in, const int* in_sizes, int n_in,
                              void* d_out, int out_size) {
    const float* audio  = (const float*)d_in[0];
    const float* window = (const float*)d_in[1];
    const float* fb     = (const float*)d_in[2];
    float* out          = (float*)d_out;

    const int smem_bytes = (SU_SIZE + NROWS * FPB * 2 + 2 * FPB) * sizeof(float);
    cudaFuncSetAttribute(melspec_kernel,
                         cudaFuncAttributeMaxDynamicSharedMemorySize,
                         smem_bytes);

    int setup_blocks = (ROWS_PAD * KPAD + 255) / 256 + 1;   // last block: mrange
    setup_kernel<<<setup_blocks, 256>>>(fb);

    dim3 grid(NTILES, NB);
    melspec_kernel<<<grid, NTHREADS, smem_bytes>>>(audio, window, fb, out);
}

// round 7
// speedup vs baseline: 1.4759x; 1.4759x over previous
#include <cuda_runtime.h>
#include <cuda_bf16.h>
#include <math.h>
#include <stdint.h>

// ---------------- problem constants ----------------
#define NB       128
#define TLEN     160000
#define NFFT     400
#define HOP      160
#define NFRAMES  1001
#define NFREQ    201
#define NMELS    80

// ---------------- GEMM tiling (mma.sync m16n8k16 bf16) ----------------
#define MTILE    64                  // frames per CTA
#define FBLK     16                  // CTAs per batch (16*64 >= 1001)
#define KDIM     208                 // padded K (n = 1..199)
#define KT       13                  // k16 tiles
#define NT       26                  // n8 tiles (bins padded to 208)
#define NTHREADS 512
#define SPAN     (HOP * (MTILE - 1) + NFFT)    // 10480
#define SWZ(i)   ((i) + ((i) >> 5))
#define PSTRIDE  209

// smem byte offsets
#define RAW_OFF  0
#define RAW_BYTES 43232              // SWZ(10479)+1 = 10806 floats -> 43224, pad
#define W_OFF    RAW_BYTES
#define A_OFF    (W_OFF + 1632)      // 44864, 16-aligned
#define APART_U32 (KT * 4 * 32 * 4)  // 6656 u32 per operand part
#define A_EHI    (A_OFF)
#define A_ELO    (A_EHI + APART_U32 * 4)
#define A_OHI    (A_ELO + APART_U32 * 4)
#define A_OLO    (A_OHI + APART_U32 * 4)
#define P_OFF    (A_OLO + APART_U32 * 4)       // 151360
#define SMEM_TOTAL (P_OFF + MTILE * PSTRIDE * 4)   // 204864

// B tables in fragment layout: [part][((nt*13+kt)*32+lane)*2+reg]
// parts: 0=cos_hi 1=cos_lo 2=sin_hi 3=sin_lo
#define BPART_U32 (NT * KT * 32 * 2)           // 21632
__device__ unsigned g_B[4][BPART_U32];
__device__ int2 g_mrange[NMELS];

__device__ __forceinline__ void bf_split(float v, unsigned short& hi, unsigned short& lo) {
    __nv_bfloat16 h = __float2bfloat16(v);
    hi = __bfloat16_as_ushort(h);
    lo = __bfloat16_as_ushort(__float2bfloat16(v - __bfloat162float(h)));
}

// ---------------- setup: B fragments + mel ranges ----------------
__global__ void setup_kernel(const float* __restrict__ fb) {
    if (blockIdx.x == gridDim.x - 1) {
        int m = threadIdx.x;
        if (m < NMELS) {
            int ks = NFREQ, ke = 0;
            for (int k = 0; k < NFREQ; k++)
                if (fb[m * NFREQ + k] != 0.0f) { if (k < ks) ks = k; ke = k + 1; }
            if (ke < ks) { ks = 0; ke = 0; }
            g_mrange[m] = make_int2(ks, ke);
        }
        return;
    }
    int id = blockIdx.x * blockDim.x + threadIdx.x;
    if (id >= 4 * BPART_U32) return;
    int part = id / BPART_U32;
    int s    = id - part * BPART_U32;
    int reg  = s & 1;
    int lane = (s >> 1) & 31;
    int t    = s >> 6;
    int kt   = t % 13;
    int nt   = t / 13;
    int p    = (reg << 2) | (lane & 3);    // k-pair index within k16 tile
    int col  = lane >> 2;
    int k0   = kt * 16 + 2 * p;
    int bin  = nt * 8 + col;
    unsigned short b0 = 0, b1 = 0;
    #pragma unroll
    for (int e = 0; e < 2; e++) {
        int n = k0 + e + 1;
        float v = 0.0f;
        if (n <= 199 && bin <= 200) {
            long long ph = ((long long)n * bin) % NFFT;
            double a = (double)ph * (6.283185307179586476925286766559 / (double)NFFT);
            v = (float)((part >= 2) ? sin(a) : cos(a));
        }
        unsigned short hi, lo;
        bf_split(v, hi, lo);
        unsigned short ev = (part & 1) ? lo : hi;
        if (e == 0) b0 = ev; else b1 = ev;
    }
    g_B[part][s] = ((unsigned)b1 << 16) | b0;
}

#define MMA(d0,d1,d2,d3, a, b) \
    asm volatile("mma.sync.aligned.m16n8k16.row.col.f32.bf16.bf16.f32 " \
        "{%0,%1,%2,%3}, {%4,%5,%6,%7}, {%8,%9}, {%0,%1,%2,%3};" \
        : "+f"(d0), "+f"(d1), "+f"(d2), "+f"(d3) \
        : "r"((a).x), "r"((a).y), "r"((a).z), "r"((a).w), "r"((b).x), "r"((b).y))

// ---------------- main kernel ----------------
__global__ __launch_bounds__(NTHREADS, 1)
void melspec_kernel(const float* __restrict__ audio,
                    const float* __restrict__ window,
                    const float* __restrict__ fb,
                    float* __restrict__ out) {
    extern __shared__ char smem[];
    float*    s_raw = (float*)(smem + RAW_OFF);
    float*    s_w   = (float*)(smem + W_OFF);
    unsigned* a_ehi = (unsigned*)(smem + A_EHI);
    unsigned* a_elo = (unsigned*)(smem + A_ELO);
    unsigned* a_ohi = (unsigned*)(smem + A_OHI);
    unsigned* a_olo = (unsigned*)(smem + A_OLO);
    float*    s_p   = (float*)(smem + P_OFF);

    const int tid    = threadIdx.x;
    const int b      = blockIdx.y;
    const int frame0 = blockIdx.x * MTILE;
    const float* x   = audio + (size_t)b * TLEN;
    const int base   = frame0 * HOP - (NFFT / 2);

    // ---- raw samples (reflect pad, swizzled) + window ----
    for (int i = tid; i < SPAN; i += NTHREADS) {
        int j = base + i;
        if (j < 0) j = -j;
        else if (j >= TLEN) j = 2 * TLEN - 2 - j;
        s_raw[SWZ(i)] = x[j];
    }
    for (int i = tid; i < NFFT; i += NTHREADS) s_w[i] = window[i];
    __syncthreads();

    // ---- build A fragments: e/o, hi/lo, in mma lane layout ----
    for (int i = tid; i < MTILE * 104; i += NTHREADS) {   // 6656 = 512*13
        int f  = i / 104;
        int kq = i - f * 104;
        int k0 = kq * 2;
        int nb = f * HOP;
        float e0 = 0.f, o0 = 0.f, e1 = 0.f, o1 = 0.f;
        int n0 = k0 + 1;
        if (n0 <= 199) {
            float w = s_w[n0];
            float a = s_raw[SWZ(nb + n0)], c = s_raw[SWZ(nb + NFFT - n0)];
            e0 = w * (a + c); o0 = w * (a - c);
        }
        int n1 = k0 + 2;
        if (n1 <= 199) {
            float w = s_w[n1];
            float a = s_raw[SWZ(nb + n1)], c = s_raw[SWZ(nb + NFFT - n1)];
            e1 = w * (a + c); o1 = w * (a - c);
        }
        unsigned short eh0, el0, eh1, el1, oh0, ol0, oh1, ol1;
        bf_split(e0, eh0, el0); bf_split(e1, eh1, el1);
        bf_split(o0, oh0, ol0); bf_split(o1, oh1, ol1);
        int kt   = k0 >> 4;
        int q    = (k0 >> 1) & 7;
        int lane = ((f & 7) << 2) | (q & 3);
        int reg  = ((f >> 3) & 1) | (((q >> 2) & 1) << 1);
        int mt   = f >> 4;
        int ai   = ((kt * 4 + mt) * 32 + lane) * 4 + reg;
        a_ehi[ai] = ((unsigned)eh1 << 16) | eh0;
        a_elo[ai] = ((unsigned)el1 << 16) | el0;
        a_ohi[ai] = ((unsigned)oh1 << 16) | oh0;
        a_olo[ai] = ((unsigned)ol1 << 16) | ol0;
    }
    __syncthreads();

    // ---- GEMM: D_re = E x COS, D_im = O x SIN  (3-pass bf16 split) ----
    {
        const int w    = tid >> 5;
        const int lane = tid & 31;
        const int mt   = w & 3;            // m16 tile
        const int nq   = w >> 2;           // n-tile stride group (0..3)
        const int fa   = mt * 16 + (lane >> 2);
        const int fb2  = fa + 8;
        const float t0a   = s_w[0]   * s_raw[SWZ(fa  * HOP)];
        const float t200a = s_w[200] * s_raw[SWZ(fa  * HOP + 200)];
        const float t0b   = s_w[0]   * s_raw[SWZ(fb2 * HOP)];
        const float t200b = s_w[200] * s_raw[SWZ(fb2 * HOP + 200)];

        for (int nt = nq; nt < NT; nt += 4) {
            float dr0 = 0.f, dr1 = 0.f, dr2 = 0.f, dr3 = 0.f;
            float di0 = 0.f, di1 = 0.f, di2 = 0.f, di3 = 0.f;
            for (int kt = 0; kt < KT; kt++) {
                int ai = ((kt * 4 + mt) * 32 + lane) * 4;
                uint4 ehi = *(const uint4*)(a_ehi + ai);
                uint4 elo = *(const uint4*)(a_elo + ai);
                uint4 ohi = *(const uint4*)(a_ohi + ai);
                uint4 olo = *(const uint4*)(a_olo + ai);
                int bi = ((nt * KT + kt) * 32 + lane) * 2;
                uint2 bch = *(const uint2*)(&g_B[0][bi]);
                uint2 bcl = *(const uint2*)(&g_B[1][bi]);
                uint2 bsh = *(const uint2*)(&g_B[2][bi]);
                uint2 bsl = *(const uint2*)(&g_B[3][bi]);
                MMA(dr0, dr1, dr2, dr3, ehi, bch);
                MMA(di0, di1, di2, di3, ohi, bsh);
                MMA(dr0, dr1, dr2, dr3, elo, bch);
                MMA(di0, di1, di2, di3, olo, bsh);
                MMA(dr0, dr1, dr2, dr3, ehi, bcl);
                MMA(di0, di1, di2, di3, ohi, bsl);
            }
            // epilogue: DC/Nyquist terms + power into smem
            int c0 = nt * 8 + ((lane & 3) << 1);
            float ra0 = dr0 + t0a + t200a;     // bin even: +x200w
            float ra1 = dr1 + t0a - t200a;     // bin odd:  -x200w
            float rb0 = dr2 + t0b + t200b;
            float rb1 = dr3 + t0b - t200b;
            if (c0 < NFREQ) {
                s_p[fa  * PSTRIDE + c0] = ra0 * ra0 + di0 * di0;
                s_p[fb2 * PSTRIDE + c0] = rb0 * rb0 + di2 * di2;
            }
            if (c0 + 1 < NFREQ) {
                s_p[fa  * PSTRIDE + c0 + 1] = ra1 * ra1 + di1 * di1;
                s_p[fb2 * PSTRIDE + c0 + 1] = rb1 * rb1 + di3 * di3;
            }
        }
    }
    __syncthreads();

    // ---- sparse mel projection + log ----
    {
        const int f   = tid & (MTILE - 1);
        const int grp = tid >> 6;                 // 0..7
        int nvalid = NFRAMES - frame0;
        if (nvalid > MTILE) nvalid = MTILE;
        const float* prow = s_p + f * PSTRIDE;
        for (int m = grp; m < NMELS; m += 8) {
            int2 r = g_mrange[m];
            float acc = 0.0f;
            const float* fbr = fb + m * NFREQ;
            for (int kk = r.x; kk < r.y; kk++)
                acc = fmaf(fbr[kk], prow[kk], acc);
            if (f < nvalid)
                out[((size_t)b * NMELS + m) * NFRAMES + frame0 + f] =
                    logf(acc + 1.1920929e-07f);
        }
    }
}

extern "C" void kernel_launch(void* const* d_in, const int* in_sizes, int n_in,
                              void* d_out, int out_size) {
    const float* audio  = (const float*)d_in[0];
    const float* window = (const float*)d_in[1];
    const float* fb     = (const float*)d_in[2];
    float* out          = (float*)d_out;

    cudaFuncSetAttribute(melspec_kernel,
                         cudaFuncAttributeMaxDynamicSharedMemorySize, SMEM_TOTAL);

    int setup_blocks = (4 * BPART_U32 + 255) / 256 + 1;
    setup_kernel<<<setup_blocks, 256>>>(fb);

    dim3 grid(FBLK, NB);
    melspec_kernel<<<grid, NTHREADS, SMEM_TOTAL>>>(audio, window, fb, out);
}

// round 8
// speedup vs baseline: 1.6840x; 1.1410x over previous
#include <cuda_runtime.h>
#include <cuda_bf16.h>
#include <math.h>
#include <stdint.h>

// ---------------- problem constants ----------------
#define NB       128
#define TLEN     160000
#define NFFT     400
#define HOP      160
#define NFRAMES  1001
#define NFREQ    201
#define NMELS    80

// ---------------- GEMM tiling (mma.sync m16n8k16 bf16) ----------------
#define MTILE    64                  // frames per CTA
#define FBLK     16                  // CTAs per batch
#define KT       13                  // k16 tiles (K = 208, n = 1..199 padded)
#define NT       28                  // n8 tiles (bins padded to 224; 7 per nq group)
#define NTHREADS 512
#define SPAN     (HOP * (MTILE - 1) + NFFT)    // 10480
#define SWZ(i)   ((i) + ((i) >> 5))
#define PSTRIDE  209

// smem byte offsets
#define RAW_BYTES 43232              // SWZ(10479)+1 floats, padded
#define W_OFF    RAW_BYTES
#define A_OFF    (W_OFF + 1632)
#define APART_U32 (KT * 4 * 32 * 4)  // 6656 u32 per operand part
#define A_EHI    (A_OFF)
#define A_ELO    (A_EHI + APART_U32 * 4)
#define A_OHI    (A_ELO + APART_U32 * 4)
#define A_OLO    (A_OHI + APART_U32 * 4)
#define P_OFF    (A_OLO + APART_U32 * 4)
#define SMEM_TOTAL (P_OFF + MTILE * PSTRIDE * 4)   // 204864

// B tables, fragment layout, hi/lo interleaved per lane:
// g_Bc/g_Bs[((nt*13+kt)*32+lane)*4 + r], r = {0,1}: hi regs, {2,3}: lo regs
#define BTAB_U32 (NT * KT * 32 * 4)            // 46592
__device__ unsigned g_Bc[BTAB_U32];
__device__ unsigned g_Bs[BTAB_U32];
__device__ int2 g_mrange[NMELS];

__device__ __forceinline__ void bf_split(float v, unsigned short& hi, unsigned short& lo) {
    __nv_bfloat16 h = __float2bfloat16(v);
    hi = __bfloat16_as_ushort(h);
    lo = __bfloat16_as_ushort(__float2bfloat16(v - __bfloat162float(h)));
}

// ---------------- setup: B fragments + mel ranges ----------------
__global__ void setup_kernel(const float* __restrict__ fb) {
    if (blockIdx.x == gridDim.x - 1) {
        int m = threadIdx.x;
        if (m < NMELS) {
            int ks = NFREQ, ke = 0;
            for (int k = 0; k < NFREQ; k++)
                if (fb[m * NFREQ + k] != 0.0f) { if (k < ks) ks = k; ke = k + 1; }
            if (ke < ks) { ks = 0; ke = 0; }
            g_mrange[m] = make_int2(ks, ke);
        }
        return;
    }
    int id = blockIdx.x * blockDim.x + threadIdx.x;
    if (id >= 2 * BTAB_U32) return;
    int trig = id / BTAB_U32;
    int s    = id - trig * BTAB_U32;
    int r    = s & 3;                  // 0,1: hi pair regs; 2,3: lo pair regs
    int lane = (s >> 2) & 31;
    int t    = s >> 7;
    int kt   = t % 13;
    int nt   = t / 13;
    int reg  = r & 1;
    int part_lo = r >> 1;
    int p    = (reg << 2) | (lane & 3);    // k-pair index within k16 tile
    int col  = lane >> 2;
    int k0   = kt * 16 + 2 * p;
    int bin  = nt * 8 + col;
    unsigned short b0 = 0, b1 = 0;
    #pragma unroll
    for (int e = 0; e < 2; e++) {
        int n = k0 + e + 1;
        float v = 0.0f;
        if (n <= 199 && bin <= 200) {
            long long ph = ((long long)n * bin) % NFFT;
            double a = (double)ph * (6.283185307179586476925286766559 / (double)NFFT);
            v = (float)(trig ? sin(a) : cos(a));
        }
        unsigned short hi, lo;
        bf_split(v, hi, lo);
        unsigned short ev = part_lo ? lo : hi;
        if (e == 0) b0 = ev; else b1 = ev;
    }
    unsigned* dst = trig ? g_Bs : g_Bc;
    dst[s] = ((unsigned)b1 << 16) | b0;
}

#define MMA4(d0,d1,d2,d3, ax,ay,az,aw, bx,by) \
    asm volatile("mma.sync.aligned.m16n8k16.row.col.f32.bf16.bf16.f32 " \
        "{%0,%1,%2,%3}, {%4,%5,%6,%7}, {%8,%9}, {%0,%1,%2,%3};" \
        : "+f"(d0), "+f"(d1), "+f"(d2), "+f"(d3) \
        : "r"(ax), "r"(ay), "r"(az), "r"(aw), "r"(bx), "r"(by))

// ---------------- main kernel ----------------
__global__ __launch_bounds__(NTHREADS, 1)
void melspec_kernel(const float* __restrict__ audio,
                    const float* __restrict__ window,
                    const float* __restrict__ fb,
                    float* __restrict__ out) {
    extern __shared__ char smem[];
    float*    s_raw = (float*)smem;
    float*    s_w   = (float*)(smem + W_OFF);
    unsigned* a_ehi = (unsigned*)(smem + A_EHI);
    unsigned* a_elo = (unsigned*)(smem + A_ELO);
    unsigned* a_ohi = (unsigned*)(smem + A_OHI);
    unsigned* a_olo = (unsigned*)(smem + A_OLO);
    float*    s_p   = (float*)(smem + P_OFF);

    const int tid    = threadIdx.x;
    const int b      = blockIdx.y;
    const int frame0 = blockIdx.x * MTILE;
    const float* x   = audio + (size_t)b * TLEN;
    const int base   = frame0 * HOP - (NFFT / 2);

    // ---- raw samples (reflect pad, swizzled) + window ----
    for (int i = tid; i < SPAN; i += NTHREADS) {
        int j = base + i;
        if (j < 0) j = -j;
        else if (j >= TLEN) j = 2 * TLEN - 2 - j;
        s_raw[SWZ(i)] = x[j];
    }
    for (int i = tid; i < NFFT; i += NTHREADS) s_w[i] = window[i];
    __syncthreads();

    // ---- build A fragments: e/o, hi/lo, in mma lane layout ----
    for (int i = tid; i < MTILE * 104; i += NTHREADS) {
        int f  = i / 104;
        int kq = i - f * 104;
        int k0 = kq * 2;
        int nb = f * HOP;
        float e0 = 0.f, o0 = 0.f, e1 = 0.f, o1 = 0.f;
        int n0 = k0 + 1;
        if (n0 <= 199) {
            float w = s_w[n0];
            float a = s_raw[SWZ(nb + n0)], c = s_raw[SWZ(nb + NFFT - n0)];
            e0 = w * (a + c); o0 = w * (a - c);
        }
        int n1 = k0 + 2;
        if (n1 <= 199) {
            float w = s_w[n1];
            float a = s_raw[SWZ(nb + n1)], c = s_raw[SWZ(nb + NFFT - n1)];
            e1 = w * (a + c); o1 = w * (a - c);
        }
        unsigned short eh0, el0, eh1, el1, oh0, ol0, oh1, ol1;
        bf_split(e0, eh0, el0); bf_split(e1, eh1, el1);
        bf_split(o0, oh0, ol0); bf_split(o1, oh1, ol1);
        int kt   = k0 >> 4;
        int q    = (k0 >> 1) & 7;
        int lane = ((f & 7) << 2) | (q & 3);
        int reg  = ((f >> 3) & 1) | (((q >> 2) & 1) << 1);
        int mt   = f >> 4;
        int ai   = ((kt * 4 + mt) * 32 + lane) * 4 + reg;
        a_ehi[ai] = ((unsigned)eh1 << 16) | eh0;
        a_elo[ai] = ((unsigned)el1 << 16) | el0;
        a_ohi[ai] = ((unsigned)oh1 << 16) | oh0;
        a_olo[ai] = ((unsigned)ol1 << 16) | ol0;
    }
    __syncthreads();

    // ---- GEMM: kt-outer, register accumulators for CNT n-tiles per chunk ----
    {
        const int w    = tid >> 5;
        const int lane = tid & 31;
        const int mt   = w & 3;            // m16 tile
        const int nq   = w >> 2;           // n group: nt = nq*7 + c, c = 0..6
        const int fa   = mt * 16 + (lane >> 2);
        const int fb2  = fa + 8;
        const float t0a   = s_w[0]   * s_raw[SWZ(fa  * HOP)];
        const float t200a = s_w[200] * s_raw[SWZ(fa  * HOP + 200)];
        const float t0b   = s_w[0]   * s_raw[SWZ(fb2 * HOP)];
        const float t200b = s_w[200] * s_raw[SWZ(fb2 * HOP + 200)];

#define GEMM_CHUNK(CNT, CBASE)                                                 \
        {                                                                      \
            float acc[CNT][8];                                                 \
            _Pragma("unroll")                                                  \
            for (int t = 0; t < CNT; t++)                                      \
                _Pragma("unroll")                                              \
                for (int j = 0; j < 8; j++) acc[t][j] = 0.0f;                  \
            for (int kt = 0; kt < KT; kt++) {                                  \
                int ai = ((kt * 4 + mt) * 32 + lane) * 4;                      \
                uint4 ehi = *(const uint4*)(a_ehi + ai);                       \
                uint4 elo = *(const uint4*)(a_elo + ai);                       \
                uint4 ohi = *(const uint4*)(a_ohi + ai);                       \
                uint4 olo = *(const uint4*)(a_olo + ai);                       \
                _Pragma("unroll")                                              \
                for (int t = 0; t < CNT; t++) {                                \
                    int nt = nq * 7 + CBASE + t;                               \
                    int bi = ((nt * KT + kt) * 32 + lane) * 4;                 \
                    uint4 bc = *(const uint4*)(g_Bc + bi);                     \
                    uint4 bs = *(const uint4*)(g_Bs + bi);                     \
                    MMA4(acc[t][0],acc[t][1],acc[t][2],acc[t][3],              \
                         ehi.x,ehi.y,ehi.z,ehi.w, bc.x,bc.y);                  \
                    MMA4(acc[t][0],acc[t][1],acc[t][2],acc[t][3],              \
                         elo.x,elo.y,elo.z,elo.w, bc.x,bc.y);                  \
                    MMA4(acc[t][0],acc[t][1],acc[t][2],acc[t][3],              \
                         ehi.x,ehi.y,ehi.z,ehi.w, bc.z,bc.w);                  \
                    MMA4(acc[t][4],acc[t][5],acc[t][6],acc[t][7],              \
                         ohi.x,ohi.y,ohi.z,ohi.w, bs.x,bs.y);                  \
                    MMA4(acc[t][4],acc[t][5],acc[t][6],acc[t][7],              \
                         olo.x,olo.y,olo.z,olo.w, bs.x,bs.y);                  \
                    MMA4(acc[t][4],acc[t][5],acc[t][6],acc[t][7],              \
                         ohi.x,ohi.y,ohi.z,ohi.w, bs.z,bs.w);                  \
                }                                                              \
            }                                                                  \
            _Pragma("unroll")                                                  \
            for (int t = 0; t < CNT; t++) {                                    \
                int c0 = (nq * 7 + CBASE + t) * 8 + ((lane & 3) << 1);         \
                float ra0 = acc[t][0] + t0a + t200a;                           \
                float ra1 = acc[t][1] + t0a - t200a;                           \
                float rb0 = acc[t][2] + t0b + t200b;                           \
                float rb1 = acc[t][3] + t0b - t200b;                           \
                if (c0 < NFREQ) {                                              \
                    s_p[fa  * PSTRIDE + c0] = ra0 * ra0 + acc[t][4]*acc[t][4]; \
                    s_p[fb2 * PSTRIDE + c0] = rb0 * rb0 + acc[t][6]*acc[t][6]; \
                }                                                              \
                if (c0 + 1 < NFREQ) {                                          \
                    s_p[fa  * PSTRIDE + c0+1] = ra1 * ra1 + acc[t][5]*acc[t][5]; \
                    s_p[fb2 * PSTRIDE + c0+1] = rb1 * rb1 + acc[t][7]*acc[t][7]; \
                }                                                              \
            }                                                                  \
        }

        GEMM_CHUNK(4, 0)
        GEMM_CHUNK(3, 4)
#undef GEMM_CHUNK
    }
    __syncthreads();

    // ---- sparse mel projection + log ----
    {
        const int f   = tid & (MTILE - 1);
        const int grp = tid >> 6;                 // 0..7
        int nvalid = NFRAMES - frame0;
        if (nvalid > MTILE) nvalid = MTILE;
        const float* prow = s_p + f * PSTRIDE;
        for (int m = grp; m < NMELS; m += 8) {
            int2 r = g_mrange[m];
            float acc = 0.0f;
            const float* fbr = fb + m * NFREQ;
            for (int kk = r.x; kk < r.y; kk++)
                acc = fmaf(fbr[kk], prow[kk], acc);
            if (f < nvalid)
                out[((size_t)b * NMELS + m) * NFRAMES + frame0 + f] =
                    logf(acc + 1.1920929e-07f);
        }
    }
}

extern "C" void kernel_launch(void* const* d_in, const int* in_sizes, int n_in,
                              void* d_out, int out_size) {
    const float* audio  = (const float*)d_in[0];
    const float* window = (const float*)d_in[1];
    const float* fb     = (const float*)d_in[2];
    float* out          = (float*)d_out;

    cudaFuncSetAttribute(melspec_kernel,
                         cudaFuncAttributeMaxDynamicSharedMemorySize, SMEM_TOTAL);

    int setup_blocks = (2 * BTAB_U32 + 255) / 256 + 1;
    setup_kernel<<<setup_blocks, 256>>>(fb);

    dim3 grid(FBLK, NB);
    melspec_kernel<<<grid, NTHREADS, SMEM_TOTAL>>>(audio, window, fb, out);
}